// round 2
// baseline (speedup 1.0000x reference)
#include <cuda_runtime.h>

#define Bb 8
#define HH 64
#define WW 64
#define CC 256
#define NHEADS 8
#define DD 32
#define NTOK (Bb*HH*WW)   // 32768
#define QSCALE 0.17677669529663687f  // 32^-0.5

// scratch: [3][B*NH][H*W][D] for q,k,v ; [NTOK][C] for attention output
__device__ float g_qkv[(size_t)3*Bb*NHEADS*HH*WW*DD];
__device__ float g_y[(size_t)NTOK*CC];

// ---------------------------------------------------------------------------
// GEMM 1: qkv = x @ w_qkv^T + b, scattered to g_qkv with q pre-scaled.
// A = x [NTOK,256] row-major, B = w [768,256] row-major. C[n,m]=sum_c A[n,c]B[m,c]
// 128x128 tile, BK=8, 256 threads, 8x8 microtile.
// ---------------------------------------------------------------------------
__global__ __launch_bounds__(256) void qkv_gemm(const float* __restrict__ x,
                                                const float* __restrict__ w,
                                                const float* __restrict__ bias) {
    __shared__ float As[8][128];
    __shared__ float Bs[8][128];
    const int n0 = blockIdx.x * 128;
    const int m0 = blockIdx.y * 128;
    const int t  = threadIdx.x;
    const int tr = t >> 4, tc = t & 15;
    const int arow = t >> 1, ac4 = (t & 1) * 4;

    float acc[8][8];
#pragma unroll
    for (int r = 0; r < 8; r++)
#pragma unroll
        for (int c = 0; c < 8; c++) acc[r][c] = 0.f;

    for (int kk = 0; kk < 256; kk += 8) {
        float4 av = *(const float4*)&x[(size_t)(n0 + arow) * 256 + kk + ac4];
        float4 bv = *(const float4*)&w[(size_t)(m0 + arow) * 256 + kk + ac4];
        __syncthreads();
        As[ac4+0][arow] = av.x; As[ac4+1][arow] = av.y;
        As[ac4+2][arow] = av.z; As[ac4+3][arow] = av.w;
        Bs[ac4+0][arow] = bv.x; Bs[ac4+1][arow] = bv.y;
        Bs[ac4+2][arow] = bv.z; Bs[ac4+3][arow] = bv.w;
        __syncthreads();
#pragma unroll
        for (int k = 0; k < 8; k++) {
            float4 a0 = *(const float4*)&As[k][tr*8];
            float4 a1 = *(const float4*)&As[k][tr*8+4];
            float4 b0 = *(const float4*)&Bs[k][tc*8];
            float4 b1 = *(const float4*)&Bs[k][tc*8+4];
            float ar[8] = {a0.x,a0.y,a0.z,a0.w,a1.x,a1.y,a1.z,a1.w};
            float br[8] = {b0.x,b0.y,b0.z,b0.w,b1.x,b1.y,b1.z,b1.w};
#pragma unroll
            for (int r = 0; r < 8; r++)
#pragma unroll
                for (int c = 0; c < 8; c++) acc[r][c] += ar[r]*br[c];
        }
    }

    // epilogue: scatter into g_qkv [tsel][b*8+head][i*64+j][d]
#pragma unroll
    for (int r = 0; r < 8; r++) {
        const int n = n0 + tr*8 + r;
        const int b = n >> 12;
        const int ij = n & 4095;
#pragma unroll
        for (int c = 0; c < 8; c++) {
            const int m = m0 + tc*8 + c;
            float val = acc[r][c] + bias[m];
            const int tsel = m >> 8;
            const int hm   = m & 255;
            const int head = hm >> 5;
            const int d    = hm & 31;
            if (tsel == 0) val *= QSCALE;
            const size_t idx = (((size_t)(tsel*64 + b*8 + head)) * 4096 + ij) * 32 + d;
            g_qkv[idx] = val;
        }
    }
}

// ---------------------------------------------------------------------------
// GEMM 2: out = g_y @ w_proj^T + b_proj
// ---------------------------------------------------------------------------
__global__ __launch_bounds__(256) void proj_gemm(const float* __restrict__ w,
                                                 const float* __restrict__ bias,
                                                 float* __restrict__ out) {
    __shared__ float As[8][128];
    __shared__ float Bs[8][128];
    const int n0 = blockIdx.x * 128;
    const int m0 = blockIdx.y * 128;
    const int t  = threadIdx.x;
    const int tr = t >> 4, tc = t & 15;
    const int arow = t >> 1, ac4 = (t & 1) * 4;

    float acc[8][8];
#pragma unroll
    for (int r = 0; r < 8; r++)
#pragma unroll
        for (int c = 0; c < 8; c++) acc[r][c] = 0.f;

    for (int kk = 0; kk < 256; kk += 8) {
        float4 av = *(const float4*)&g_y[(size_t)(n0 + arow) * 256 + kk + ac4];
        float4 bv = *(const float4*)&w[(size_t)(m0 + arow) * 256 + kk + ac4];
        __syncthreads();
        As[ac4+0][arow] = av.x; As[ac4+1][arow] = av.y;
        As[ac4+2][arow] = av.z; As[ac4+3][arow] = av.w;
        Bs[ac4+0][arow] = bv.x; Bs[ac4+1][arow] = bv.y;
        Bs[ac4+2][arow] = bv.z; Bs[ac4+3][arow] = bv.w;
        __syncthreads();
#pragma unroll
        for (int k = 0; k < 8; k++) {
            float4 a0 = *(const float4*)&As[k][tr*8];
            float4 a1 = *(const float4*)&As[k][tr*8+4];
            float4 b0 = *(const float4*)&Bs[k][tc*8];
            float4 b1 = *(const float4*)&Bs[k][tc*8+4];
            float ar[8] = {a0.x,a0.y,a0.z,a0.w,a1.x,a1.y,a1.z,a1.w};
            float br[8] = {b0.x,b0.y,b0.z,b0.w,b1.x,b1.y,b1.z,b1.w};
#pragma unroll
            for (int r = 0; r < 8; r++)
#pragma unroll
                for (int c = 0; c < 8; c++) acc[r][c] += ar[r]*br[c];
        }
    }

#pragma unroll
    for (int r = 0; r < 8; r++) {
        const int n = n0 + tr*8 + r;
#pragma unroll
        for (int c = 0; c < 8; c++) {
            const int m = m0 + tc*8 + c;
            out[(size_t)n*256 + m] = acc[r][c] + bias[m];
        }
    }
}

// ---------------------------------------------------------------------------
// Neighborhood attention. One block = (b, head_local, image row i), 64 threads,
// lane t = query column j. Online softmax over the KxK window, streaming one
// key/value image row (staged in smem) per ki.
// ---------------------------------------------------------------------------
template<int K>
__global__ __launch_bounds__(64) void na_attn(const float* __restrict__ rpb,
                                              int head_base) {
    constexpr int R  = 2*K - 1;
    constexpr int NHf = K/2;
    __shared__ float sk[64*36];
    __shared__ float sv[64*36];
    __shared__ float sb[R*R];

    const int i  = blockIdx.x;
    const int hl = blockIdx.y;
    const int b  = blockIdx.z;
    const int head = head_base + hl;
    const int t = threadIdx.x;   // query column j

    for (int u = t; u < R*R; u += 64) sb[u] = rpb[(size_t)hl*R*R + u];

    const int bh = b*NHEADS + head;
    const float* qb = g_qkv + ((size_t)(      bh) * 4096) * 32;
    const float* kb = g_qkv + ((size_t)( 64 + bh) * 4096) * 32;
    const float* vb = g_qkv + ((size_t)(128 + bh) * 4096) * 32;

    float4 q[8];
    {
        const float4* qp = (const float4*)(qb + ((size_t)i*64 + t)*32);
#pragma unroll
        for (int u = 0; u < 8; u++) q[u] = qp[u];
    }

    const int si  = min(max(i - NHf, 0), HH - K);
    const int sj  = min(max(t - NHf, 0), WW - K);
    const int pbi = si - i + K - 1;
    const int pbj = sj - t + K - 1;

    float m = -1e30f, s = 0.f;
    float acc[32];
#pragma unroll
    for (int u = 0; u < 32; u++) acc[u] = 0.f;

#pragma unroll 1
    for (int ki = 0; ki < K; ki++) {
        const int row = si + ki;
        const float* krow = kb + ((size_t)row*64)*32;
        const float* vrow = vb + ((size_t)row*64)*32;
        __syncthreads();
#pragma unroll
        for (int u = 0; u < 8; u++) {
            const int idx = u*256 + t*4;           // 0..2047 coalesced
            const int col = idx >> 5, d = idx & 31;
            *(float4*)&sk[col*36 + d] = *(const float4*)&krow[idx];
            *(float4*)&sv[col*36 + d] = *(const float4*)&vrow[idx];
        }
        __syncthreads();

        const float* brow = &sb[(pbi + ki)*R + pbj];
        for (int kj = 0; kj < K; kj++) {
            const float* kp = &sk[(sj + kj)*36];
            float dot = 0.f;
#pragma unroll
            for (int u = 0; u < 8; u++) {
                float4 kv4 = *(const float4*)&kp[u*4];
                dot += q[u].x*kv4.x + q[u].y*kv4.y + q[u].z*kv4.z + q[u].w*kv4.w;
            }
            const float logit = dot + brow[kj];
            const float mn = fmaxf(m, logit);
            const float f  = __expf(m - mn);
            const float p  = __expf(logit - mn);
            s = s*f + p;
            m = mn;
            const float* vp = &sv[(sj + kj)*36];
#pragma unroll
            for (int u = 0; u < 32; u += 4) {
                float4 vv = *(const float4*)&vp[u];
                acc[u+0] = acc[u+0]*f + p*vv.x;
                acc[u+1] = acc[u+1]*f + p*vv.y;
                acc[u+2] = acc[u+2]*f + p*vv.z;
                acc[u+3] = acc[u+3]*f + p*vv.w;
            }
        }
    }

    const float inv = 1.f / s;
    float* op = g_y + (((size_t)b*4096) + i*64 + t)*256 + head*32;
#pragma unroll
    for (int u = 0; u < 32; u += 4) {
        float4 o;
        o.x = acc[u+0]*inv; o.y = acc[u+1]*inv;
        o.z = acc[u+2]*inv; o.w = acc[u+3]*inv;
        *(float4*)&op[u] = o;
    }
}

// ---------------------------------------------------------------------------
extern "C" void kernel_launch(void* const* d_in, const int* in_sizes, int n_in,
                              void* d_out, int out_size) {
    const float* x      = (const float*)d_in[0];
    const float* w_qkv  = (const float*)d_in[1];
    const float* b_qkv  = (const float*)d_in[2];
    const float* rpb0   = (const float*)d_in[3];
    const float* rpb1   = (const float*)d_in[4];
    const float* w_proj = (const float*)d_in[5];
    const float* b_proj = (const float*)d_in[6];
    float* out = (float*)d_out;

    dim3 g1(NTOK/128, 768/128);
    qkv_gemm<<<g1, 256>>>(x, w_qkv, b_qkv);

    dim3 ga(HH, NHEADS/2, Bb);
    na_attn<7><<<ga, 64>>>(rpb0, 0);
    na_attn<13><<<ga, 64>>>(rpb1, 4);

    dim3 g2(NTOK/128, 256/128);
    proj_gemm<<<g2, 256>>>(w_proj, b_proj, out);
}

// round 5
// speedup vs baseline: 1.2830x; 1.2830x over previous
#include <cuda_runtime.h>

#define Bb 8
#define HH 64
#define WW 64
#define CC 256
#define NHEADS 8
#define DD 32
#define NTOK (Bb*HH*WW)   // 32768
#define QSCALE 0.17677669529663687f  // 32^-0.5

// scratch: [3][B*NH][H*W][D] for q,k,v ; [NTOK][C] for attention output
__device__ float g_qkv[(size_t)3*Bb*NHEADS*HH*WW*DD];
__device__ float g_y[(size_t)NTOK*CC];

// ---------------------------------------------------------------------------
// Double-buffered 128x128x16 SGEMM core, 256 threads, 8x8 microtile split as
// 4+4 (rows tr*4 / 64+tr*4, cols tc*4 / 64+tc*4) for conflict-free LDS.128.
// A = [N,256] row-major, B = [M,256] row-major, C[n,m] = sum_c A[n,c]*B[m,c].
// ---------------------------------------------------------------------------

#define GEMM_MAINLOOP(APTR, BPTR)                                              \
    __shared__ float As[2][16][132];                                           \
    __shared__ float Bs[2][16][132];                                           \
    const int n0 = blockIdx.x * 128;                                           \
    const int m0 = blockIdx.y * 128;                                           \
    const int t  = threadIdx.x;                                                \
    const int tr = t >> 4, tc = t & 15;                                        \
    const int lrow = t >> 2;           /* 0..63 */                             \
    const int lcol = (t & 3) * 4;      /* 0,4,8,12 */                          \
    float acc[8][8];                                                           \
    _Pragma("unroll")                                                          \
    for (int r = 0; r < 8; r++)                                                \
        _Pragma("unroll")                                                      \
        for (int c = 0; c < 8; c++) acc[r][c] = 0.f;                           \
    const float* Ag0 = APTR + (size_t)(n0 + lrow)      * 256 + lcol;           \
    const float* Ag1 = APTR + (size_t)(n0 + lrow + 64) * 256 + lcol;           \
    const float* Bg0 = BPTR + (size_t)(m0 + lrow)      * 256 + lcol;           \
    const float* Bg1 = BPTR + (size_t)(m0 + lrow + 64) * 256 + lcol;           \
    float4 a0v, a1v, b0v, b1v;                                                 \
    a0v = *(const float4*)(Ag0); a1v = *(const float4*)(Ag1);                  \
    b0v = *(const float4*)(Bg0); b1v = *(const float4*)(Bg1);                  \
    {                                                                          \
        As[0][lcol+0][lrow] = a0v.x; As[0][lcol+1][lrow] = a0v.y;              \
        As[0][lcol+2][lrow] = a0v.z; As[0][lcol+3][lrow] = a0v.w;              \
        As[0][lcol+0][lrow+64] = a1v.x; As[0][lcol+1][lrow+64] = a1v.y;        \
        As[0][lcol+2][lrow+64] = a1v.z; As[0][lcol+3][lrow+64] = a1v.w;        \
        Bs[0][lcol+0][lrow] = b0v.x; Bs[0][lcol+1][lrow] = b0v.y;              \
        Bs[0][lcol+2][lrow] = b0v.z; Bs[0][lcol+3][lrow] = b0v.w;              \
        Bs[0][lcol+0][lrow+64] = b1v.x; Bs[0][lcol+1][lrow+64] = b1v.y;        \
        Bs[0][lcol+2][lrow+64] = b1v.z; Bs[0][lcol+3][lrow+64] = b1v.w;        \
    }                                                                          \
    __syncthreads();                                                           \
    int buf = 0;                                                               \
    for (int kk = 16; kk < 256; kk += 16) {                                    \
        a0v = *(const float4*)(Ag0 + kk); a1v = *(const float4*)(Ag1 + kk);    \
        b0v = *(const float4*)(Bg0 + kk); b1v = *(const float4*)(Bg1 + kk);    \
        _Pragma("unroll")                                                      \
        for (int k = 0; k < 16; k++) {                                         \
            float4 ra0 = *(const float4*)&As[buf][k][tr*4];                    \
            float4 ra1 = *(const float4*)&As[buf][k][64 + tr*4];               \
            float4 rb0 = *(const float4*)&Bs[buf][k][tc*4];                    \
            float4 rb1 = *(const float4*)&Bs[buf][k][64 + tc*4];               \
            float ar[8] = {ra0.x,ra0.y,ra0.z,ra0.w,ra1.x,ra1.y,ra1.z,ra1.w};   \
            float br[8] = {rb0.x,rb0.y,rb0.z,rb0.w,rb1.x,rb1.y,rb1.z,rb1.w};   \
            _Pragma("unroll")                                                  \
            for (int r = 0; r < 8; r++)                                        \
                _Pragma("unroll")                                              \
                for (int c = 0; c < 8; c++) acc[r][c] += ar[r]*br[c];          \
        }                                                                      \
        const int nb = buf ^ 1;                                                \
        As[nb][lcol+0][lrow] = a0v.x; As[nb][lcol+1][lrow] = a0v.y;            \
        As[nb][lcol+2][lrow] = a0v.z; As[nb][lcol+3][lrow] = a0v.w;            \
        As[nb][lcol+0][lrow+64] = a1v.x; As[nb][lcol+1][lrow+64] = a1v.y;      \
        As[nb][lcol+2][lrow+64] = a1v.z; As[nb][lcol+3][lrow+64] = a1v.w;      \
        Bs[nb][lcol+0][lrow] = b0v.x; Bs[nb][lcol+1][lrow] = b0v.y;            \
        Bs[nb][lcol+2][lrow] = b0v.z; Bs[nb][lcol+3][lrow] = b0v.w;            \
        Bs[nb][lcol+0][lrow+64] = b1v.x; Bs[nb][lcol+1][lrow+64] = b1v.y;      \
        Bs[nb][lcol+2][lrow+64] = b1v.z; Bs[nb][lcol+3][lrow+64] = b1v.w;      \
        __syncthreads();                                                       \
        buf = nb;                                                              \
    }                                                                          \
    _Pragma("unroll")                                                          \
    for (int k = 0; k < 16; k++) {                                             \
        float4 ra0 = *(const float4*)&As[buf][k][tr*4];                        \
        float4 ra1 = *(const float4*)&As[buf][k][64 + tr*4];                   \
        float4 rb0 = *(const float4*)&Bs[buf][k][tc*4];                        \
        float4 rb1 = *(const float4*)&Bs[buf][k][64 + tc*4];                   \
        float ar[8] = {ra0.x,ra0.y,ra0.z,ra0.w,ra1.x,ra1.y,ra1.z,ra1.w};       \
        float br[8] = {rb0.x,rb0.y,rb0.z,rb0.w,rb1.x,rb1.y,rb1.z,rb1.w};       \
        _Pragma("unroll")                                                      \
        for (int r = 0; r < 8; r++)                                            \
            _Pragma("unroll")                                                  \
            for (int c = 0; c < 8; c++) acc[r][c] += ar[r]*br[c];              \
    }

// row/col index helpers for the split microtile
#define MT_ROW(r) ((r) < 4 ? (tr*4 + (r)) : (64 + tr*4 + (r) - 4))
#define MT_COL(c) ((c) < 4 ? (tc*4 + (c)) : (64 + tc*4 + (c) - 4))

// ---------------------------------------------------------------------------
// GEMM 1: qkv = x @ w_qkv^T + b, scattered to g_qkv with q pre-scaled.
// ---------------------------------------------------------------------------
__global__ __launch_bounds__(256, 2) void qkv_gemm(const float* __restrict__ x,
                                                   const float* __restrict__ w,
                                                   const float* __restrict__ bias) {
    GEMM_MAINLOOP(x, w)

    // epilogue: scatter into g_qkv [tsel][b*8+head][i*64+j][d]
#pragma unroll
    for (int r = 0; r < 8; r++) {
        const int n = n0 + MT_ROW(r);
        const int b = n >> 12;
        const int ij = n & 4095;
#pragma unroll
        for (int c = 0; c < 8; c++) {
            const int m = m0 + MT_COL(c);
            float val = acc[r][c] + bias[m];
            const int tsel = m >> 8;
            const int hm   = m & 255;
            const int head = hm >> 5;
            const int d    = hm & 31;
            if (tsel == 0) val *= QSCALE;
            const size_t idx = (((size_t)(tsel*64 + b*8 + head)) * 4096 + ij) * 32 + d;
            g_qkv[idx] = val;
        }
    }
}

// ---------------------------------------------------------------------------
// GEMM 2: out = g_y @ w_proj^T + b_proj
// ---------------------------------------------------------------------------
__global__ __launch_bounds__(256, 2) void proj_gemm(const float* __restrict__ w,
                                                    const float* __restrict__ bias,
                                                    float* __restrict__ out) {
    GEMM_MAINLOOP(g_y, w)

    float4 bv0 = *(const float4*)&bias[m0 + tc*4];
    float4 bv1 = *(const float4*)&bias[m0 + 64 + tc*4];
#pragma unroll
    for (int r = 0; r < 8; r++) {
        const int n = n0 + MT_ROW(r);
        float4 o0, o1;
        o0.x = acc[r][0] + bv0.x; o0.y = acc[r][1] + bv0.y;
        o0.z = acc[r][2] + bv0.z; o0.w = acc[r][3] + bv0.w;
        o1.x = acc[r][4] + bv1.x; o1.y = acc[r][5] + bv1.y;
        o1.z = acc[r][6] + bv1.z; o1.w = acc[r][7] + bv1.w;
        *(float4*)&out[(size_t)n*256 + m0 + tc*4]      = o0;
        *(float4*)&out[(size_t)n*256 + m0 + 64 + tc*4] = o1;
    }
}

// ---------------------------------------------------------------------------
// Neighborhood attention. One block = (b, head, image row i), 64 threads,
// lane t = query column j. Online softmax over the KxK window, streaming one
// key/value image row (staged in smem) per ki. K=7 and K=13 fused in one
// launch, dispatched on blockIdx.y.
// ---------------------------------------------------------------------------
template<int K>
__device__ __forceinline__ void na_attn_body(const float* __restrict__ rpb,
                                             int hl, int head,
                                             float* sk, float* sv, float* sb) {
    constexpr int R  = 2*K - 1;
    constexpr int NHf = K/2;

    const int i  = blockIdx.x;
    const int b  = blockIdx.z;
    const int t = threadIdx.x;   // query column j

    for (int u = t; u < R*R; u += 64) sb[u] = rpb[(size_t)hl*R*R + u];

    const int bh = b*NHEADS + head;
    const float* qb = g_qkv + ((size_t)(      bh) * 4096) * 32;
    const float* kb = g_qkv + ((size_t)( 64 + bh) * 4096) * 32;
    const float* vb = g_qkv + ((size_t)(128 + bh) * 4096) * 32;

    float4 q[8];
    {
        const float4* qp = (const float4*)(qb + ((size_t)i*64 + t)*32);
#pragma unroll
        for (int u = 0; u < 8; u++) q[u] = qp[u];
    }

    const int si  = min(max(i - NHf, 0), HH - K);
    const int sj  = min(max(t - NHf, 0), WW - K);
    const int pbi = si - i + K - 1;
    const int pbj = sj - t + K - 1;

    float m = -1e30f, s = 0.f;
    float acc[32];
#pragma unroll
    for (int u = 0; u < 32; u++) acc[u] = 0.f;

#pragma unroll 1
    for (int ki = 0; ki < K; ki++) {
        const int row = si + ki;
        const float* krow = kb + ((size_t)row*64)*32;
        const float* vrow = vb + ((size_t)row*64)*32;
        __syncthreads();
#pragma unroll
        for (int u = 0; u < 8; u++) {
            const int idx = u*256 + t*4;           // 0..2047 coalesced
            const int col = idx >> 5, d = idx & 31;
            *(float4*)&sk[col*36 + d] = *(const float4*)&krow[idx];
            *(float4*)&sv[col*36 + d] = *(const float4*)&vrow[idx];
        }
        __syncthreads();

        const float* brow = &sb[(pbi + ki)*R + pbj];
        for (int kj = 0; kj < K; kj++) {
            const float* kp = &sk[(sj + kj)*36];
            float dot = 0.f;
#pragma unroll
            for (int u = 0; u < 8; u++) {
                float4 kv4 = *(const float4*)&kp[u*4];
                dot += q[u].x*kv4.x + q[u].y*kv4.y + q[u].z*kv4.z + q[u].w*kv4.w;
            }
            const float logit = dot + brow[kj];
            const float mn = fmaxf(m, logit);
            const float f  = __expf(m - mn);
            const float p  = __expf(logit - mn);
            s = s*f + p;
            m = mn;
            const float* vp = &sv[(sj + kj)*36];
#pragma unroll
            for (int u = 0; u < 32; u += 4) {
                float4 vv = *(const float4*)&vp[u];
                acc[u+0] = acc[u+0]*f + p*vv.x;
                acc[u+1] = acc[u+1]*f + p*vv.y;
                acc[u+2] = acc[u+2]*f + p*vv.z;
                acc[u+3] = acc[u+3]*f + p*vv.w;
            }
        }
    }

    const float inv = 1.f / s;
    float* op = g_y + (((size_t)b*4096) + i*64 + t)*256 + head*32;
#pragma unroll
    for (int u = 0; u < 32; u += 4) {
        float4 o;
        o.x = acc[u+0]*inv; o.y = acc[u+1]*inv;
        o.z = acc[u+2]*inv; o.w = acc[u+3]*inv;
        *(float4*)&op[u] = o;
    }
}

__global__ __launch_bounds__(64) void na_attn_fused(const float* __restrict__ rpb0,
                                                    const float* __restrict__ rpb1) {
    __shared__ float sk[64*36];
    __shared__ float sv[64*36];
    __shared__ float sb[25*25];
    const int hy = blockIdx.y;
    if (hy < 4) {
        na_attn_body<7>(rpb0, hy, hy, sk, sv, sb);
    } else {
        na_attn_body<13>(rpb1, hy - 4, hy, sk, sv, sb);
    }
}

// ---------------------------------------------------------------------------
extern "C" void kernel_launch(void* const* d_in, const int* in_sizes, int n_in,
                              void* d_out, int out_size) {
    const float* x      = (const float*)d_in[0];
    const float* w_qkv  = (const float*)d_in[1];
    const float* b_qkv  = (const float*)d_in[2];
    const float* rpb0   = (const float*)d_in[3];
    const float* rpb1   = (const float*)d_in[4];
    const float* w_proj = (const float*)d_in[5];
    const float* b_proj = (const float*)d_in[6];
    float* out = (float*)d_out;

    dim3 g1(NTOK/128, 768/128);
    qkv_gemm<<<g1, 256>>>(x, w_qkv, b_qkv);

    dim3 ga(HH, NHEADS, Bb);
    na_attn_fused<<<ga, 64>>>(rpb0, rpb1);

    dim3 g2(NTOK/128, 256/128);
    proj_gemm<<<g2, 256>>>(w_proj, b_proj, out);
}

// round 9
// speedup vs baseline: 1.3355x; 1.0410x over previous
#include <cuda_runtime.h>
#include <cstdint>

#define Bb 8
#define HH 64
#define WW 64
#define CC 256
#define NHEADS 8
#define DD 32
#define NTOK (Bb*HH*WW)   // 32768
#define QSCALE 0.17677669529663687f  // 32^-0.5

// scratch: [3][B*NH][H*W][D] for q,k,v ; [NTOK][C] for attention output
__device__ float g_qkv[(size_t)3*Bb*NHEADS*HH*WW*DD];
__device__ float g_y[(size_t)NTOK*CC];

// ---- packed f32x2 helpers (Blackwell 2x FP32 path; bitwise == 2x scalar) ----
#define PK2(d, lo, hi)  asm("mov.b64 %0, {%1, %2};" : "=l"(d) : "f"(lo), "f"(hi))
#define UPK2(lo, hi, s) asm("mov.b64 {%0, %1}, %2;" : "=f"(lo), "=f"(hi) : "l"(s))
#define FMA2(d, a, b, c) asm("fma.rn.f32x2 %0, %1, %2, %3;" : "=l"(d) : "l"(a), "l"(b), "l"(c))
#define MUL2(d, a, b)    asm("mul.rn.f32x2 %0, %1, %2;"     : "=l"(d) : "l"(a), "l"(b))
#define ADD2(d, a, b)    asm("add.rn.f32x2 %0, %1, %2;"     : "=l"(d) : "l"(a), "l"(b))

// ---------------------------------------------------------------------------
// Double-buffered 128x128x16 SGEMM core, 256 threads, 8x8 microtile split as
// 4+4 (rows tr*4 / 64+tr*4, cols tc*4 / 64+tc*4), inner product in f32x2.
// A = [N,256] row-major, B = [M,256] row-major, C[n,m] = sum_c A[n,c]*B[m,c].
// ---------------------------------------------------------------------------
#define GEMM_MAINLOOP(APTR, BPTR)                                              \
    __shared__ float As[2][16][132];                                           \
    __shared__ float Bs[2][16][132];                                           \
    const int n0 = blockIdx.x * 128;                                           \
    const int m0 = blockIdx.y * 128;                                           \
    const int t  = threadIdx.x;                                                \
    const int tr = t >> 4, tc = t & 15;                                        \
    const int lrow = t >> 2;           /* 0..63 */                             \
    const int lcol = (t & 3) * 4;      /* 0,4,8,12 */                          \
    unsigned long long accp[8][4];                                             \
    _Pragma("unroll")                                                          \
    for (int r = 0; r < 8; r++)                                                \
        _Pragma("unroll")                                                      \
        for (int c = 0; c < 4; c++) accp[r][c] = 0ull;                         \
    const float* Ag0 = APTR + (size_t)(n0 + lrow)      * 256 + lcol;           \
    const float* Ag1 = APTR + (size_t)(n0 + lrow + 64) * 256 + lcol;           \
    const float* Bg0 = BPTR + (size_t)(m0 + lrow)      * 256 + lcol;           \
    const float* Bg1 = BPTR + (size_t)(m0 + lrow + 64) * 256 + lcol;           \
    float4 a0v, a1v, b0v, b1v;                                                 \
    a0v = *(const float4*)(Ag0); a1v = *(const float4*)(Ag1);                  \
    b0v = *(const float4*)(Bg0); b1v = *(const float4*)(Bg1);                  \
    {                                                                          \
        As[0][lcol+0][lrow] = a0v.x; As[0][lcol+1][lrow] = a0v.y;              \
        As[0][lcol+2][lrow] = a0v.z; As[0][lcol+3][lrow] = a0v.w;              \
        As[0][lcol+0][lrow+64] = a1v.x; As[0][lcol+1][lrow+64] = a1v.y;        \
        As[0][lcol+2][lrow+64] = a1v.z; As[0][lcol+3][lrow+64] = a1v.w;        \
        Bs[0][lcol+0][lrow] = b0v.x; Bs[0][lcol+1][lrow] = b0v.y;              \
        Bs[0][lcol+2][lrow] = b0v.z; Bs[0][lcol+3][lrow] = b0v.w;              \
        Bs[0][lcol+0][lrow+64] = b1v.x; Bs[0][lcol+1][lrow+64] = b1v.y;        \
        Bs[0][lcol+2][lrow+64] = b1v.z; Bs[0][lcol+3][lrow+64] = b1v.w;        \
    }                                                                          \
    __syncthreads();                                                           \
    int buf = 0;                                                               \
    for (int kk = 16; kk < 256; kk += 16) {                                    \
        a0v = *(const float4*)(Ag0 + kk); a1v = *(const float4*)(Ag1 + kk);    \
        b0v = *(const float4*)(Bg0 + kk); b1v = *(const float4*)(Bg1 + kk);    \
        _Pragma("unroll")                                                      \
        for (int k = 0; k < 16; k++) {                                         \
            float4 ra0 = *(const float4*)&As[buf][k][tr*4];                    \
            float4 ra1 = *(const float4*)&As[buf][k][64 + tr*4];               \
            ulonglong2 rb0 = *(const ulonglong2*)&Bs[buf][k][tc*4];            \
            ulonglong2 rb1 = *(const ulonglong2*)&Bs[buf][k][64 + tc*4];       \
            float ar[8] = {ra0.x,ra0.y,ra0.z,ra0.w,ra1.x,ra1.y,ra1.z,ra1.w};   \
            _Pragma("unroll")                                                  \
            for (int r = 0; r < 8; r++) {                                      \
                unsigned long long ad;                                         \
                PK2(ad, ar[r], ar[r]);                                         \
                FMA2(accp[r][0], ad, rb0.x, accp[r][0]);                       \
                FMA2(accp[r][1], ad, rb0.y, accp[r][1]);                       \
                FMA2(accp[r][2], ad, rb1.x, accp[r][2]);                       \
                FMA2(accp[r][3], ad, rb1.y, accp[r][3]);                       \
            }                                                                  \
        }                                                                      \
        const int nb = buf ^ 1;                                                \
        As[nb][lcol+0][lrow] = a0v.x; As[nb][lcol+1][lrow] = a0v.y;            \
        As[nb][lcol+2][lrow] = a0v.z; As[nb][lcol+3][lrow] = a0v.w;            \
        As[nb][lcol+0][lrow+64] = a1v.x; As[nb][lcol+1][lrow+64] = a1v.y;      \
        As[nb][lcol+2][lrow+64] = a1v.z; As[nb][lcol+3][lrow+64] = a1v.w;      \
        Bs[nb][lcol+0][lrow] = b0v.x; Bs[nb][lcol+1][lrow] = b0v.y;            \
        Bs[nb][lcol+2][lrow] = b0v.z; Bs[nb][lcol+3][lrow] = b0v.w;            \
        Bs[nb][lcol+0][lrow+64] = b1v.x; Bs[nb][lcol+1][lrow+64] = b1v.y;      \
        Bs[nb][lcol+2][lrow+64] = b1v.z; Bs[nb][lcol+3][lrow+64] = b1v.w;      \
        __syncthreads();                                                       \
        buf = nb;                                                              \
    }                                                                          \
    _Pragma("unroll")                                                          \
    for (int k = 0; k < 16; k++) {                                             \
        float4 ra0 = *(const float4*)&As[buf][k][tr*4];                        \
        float4 ra1 = *(const float4*)&As[buf][k][64 + tr*4];                   \
        ulonglong2 rb0 = *(const ulonglong2*)&Bs[buf][k][tc*4];                \
        ulonglong2 rb1 = *(const ulonglong2*)&Bs[buf][k][64 + tc*4];           \
        float ar[8] = {ra0.x,ra0.y,ra0.z,ra0.w,ra1.x,ra1.y,ra1.z,ra1.w};       \
        _Pragma("unroll")                                                      \
        for (int r = 0; r < 8; r++) {                                          \
            unsigned long long ad;                                             \
            PK2(ad, ar[r], ar[r]);                                             \
            FMA2(accp[r][0], ad, rb0.x, accp[r][0]);                           \
            FMA2(accp[r][1], ad, rb0.y, accp[r][1]);                           \
            FMA2(accp[r][2], ad, rb1.x, accp[r][2]);                           \
            FMA2(accp[r][3], ad, rb1.y, accp[r][3]);                           \
        }                                                                      \
    }                                                                          \
    float acc[8][8];                                                           \
    _Pragma("unroll")                                                          \
    for (int r = 0; r < 8; r++)                                                \
        _Pragma("unroll")                                                      \
        for (int c = 0; c < 4; c++)                                            \
            UPK2(acc[r][2*c], acc[r][2*c+1], accp[r][c]);

// row/col index helpers for the split microtile
#define MT_ROW(r) ((r) < 4 ? (tr*4 + (r)) : (64 + tr*4 + (r) - 4))
#define MT_COL(c) ((c) < 4 ? (tc*4 + (c)) : (64 + tc*4 + (c) - 4))

// ---------------------------------------------------------------------------
// GEMM 1: qkv = x @ w_qkv^T + b, scattered to g_qkv with q pre-scaled.
// ---------------------------------------------------------------------------
__global__ __launch_bounds__(256, 2) void qkv_gemm(const float* __restrict__ x,
                                                   const float* __restrict__ w,
                                                   const float* __restrict__ bias) {
    GEMM_MAINLOOP(x, w)

    // epilogue: scatter into g_qkv [tsel][b*8+head][i*64+j][d]
#pragma unroll
    for (int r = 0; r < 8; r++) {
        const int n = n0 + MT_ROW(r);
        const int b = n >> 12;
        const int ij = n & 4095;
#pragma unroll
        for (int c = 0; c < 8; c++) {
            const int m = m0 + MT_COL(c);
            float val = acc[r][c] + bias[m];
            const int tsel = m >> 8;
            const int hm   = m & 255;
            const int head = hm >> 5;
            const int d    = hm & 31;
            if (tsel == 0) val *= QSCALE;
            const size_t idx = (((size_t)(tsel*64 + b*8 + head)) * 4096 + ij) * 32 + d;
            g_qkv[idx] = val;
        }
    }
}

// ---------------------------------------------------------------------------
// GEMM 2: out = g_y @ w_proj^T + b_proj
// ---------------------------------------------------------------------------
__global__ __launch_bounds__(256, 2) void proj_gemm(const float* __restrict__ w,
                                                    const float* __restrict__ bias,
                                                    float* __restrict__ out) {
    GEMM_MAINLOOP(g_y, w)

    float4 bv0 = *(const float4*)&bias[m0 + tc*4];
    float4 bv1 = *(const float4*)&bias[m0 + 64 + tc*4];
#pragma unroll
    for (int r = 0; r < 8; r++) {
        const int n = n0 + MT_ROW(r);
        float4 o0, o1;
        o0.x = acc[r][0] + bv0.x; o0.y = acc[r][1] + bv0.y;
        o0.z = acc[r][2] + bv0.z; o0.w = acc[r][3] + bv0.w;
        o1.x = acc[r][4] + bv1.x; o1.y = acc[r][5] + bv1.y;
        o1.z = acc[r][6] + bv1.z; o1.w = acc[r][7] + bv1.w;
        *(float4*)&out[(size_t)n*256 + m0 + tc*4]      = o0;
        *(float4*)&out[(size_t)n*256 + m0 + 64 + tc*4] = o1;
    }
}

// ---------------------------------------------------------------------------
// Neighborhood attention, row-batched softmax, f32x2 math. One block =
// (b, head, image row i), 64 threads, lane t = query column j.
// Per key-row: all K logits first, one max-update+rescale, then p*V.
// ---------------------------------------------------------------------------
template<int K>
__device__ __forceinline__ void na_attn_body(const float* __restrict__ rpb,
                                             int hl, int head,
                                             float* sk, float* sv, float* sb) {
    constexpr int R  = 2*K - 1;
    constexpr int NHf = K/2;

    const int i  = blockIdx.x;
    const int b  = blockIdx.z;
    const int t = threadIdx.x;   // query column j

    for (int u = t; u < R*R; u += 64) sb[u] = rpb[(size_t)hl*R*R + u];

    const int bh = b*NHEADS + head;
    const float* qb = g_qkv + ((size_t)(      bh) * 4096) * 32;
    const float* kb = g_qkv + ((size_t)( 64 + bh) * 4096) * 32;
    const float* vb = g_qkv + ((size_t)(128 + bh) * 4096) * 32;

    ulonglong2 q2[8];   // 32 q floats as 16 f32x2 pairs
    {
        const ulonglong2* qp = (const ulonglong2*)(qb + ((size_t)i*64 + t)*32);
#pragma unroll
        for (int u = 0; u < 8; u++) q2[u] = qp[u];
    }

    const int si  = min(max(i - NHf, 0), HH - K);
    const int sj  = min(max(t - NHf, 0), WW - K);
    const int pbi = si - i + K - 1;
    const int pbj = sj - t + K - 1;

    float m = -1e30f, s = 0.f;
    unsigned long long accp[16];
#pragma unroll
    for (int u = 0; u < 16; u++) accp[u] = 0ull;

#pragma unroll 1
    for (int ki = 0; ki < K; ki++) {
        const int row = si + ki;
        const float* krow = kb + ((size_t)row*64)*32;
        const float* vrow = vb + ((size_t)row*64)*32;
        __syncthreads();
#pragma unroll
        for (int u = 0; u < 8; u++) {
            const int idx = u*256 + t*4;           // 0..2047 coalesced
            const int col = idx >> 5, dd = idx & 31;
            *(float4*)&sk[col*36 + dd] = *(const float4*)&krow[idx];
            *(float4*)&sv[col*36 + dd] = *(const float4*)&vrow[idx];
        }
        __syncthreads();

        const float* brow = &sb[(pbi + ki)*R + pbj];
        float lg[K];
        float rmax = -1e30f;
#pragma unroll
        for (int kj = 0; kj < K; kj++) {
            const ulonglong2* kp2 = (const ulonglong2*)&sk[(sj + kj)*36];
            unsigned long long d0 = 0ull, d1 = 0ull;
#pragma unroll
            for (int u = 0; u < 8; u++) {
                ulonglong2 kv = kp2[u];
                FMA2(d0, q2[u].x, kv.x, d0);
                FMA2(d1, q2[u].y, kv.y, d1);
            }
            unsigned long long ds;
            ADD2(ds, d0, d1);
            float dlo, dhi;
            UPK2(dlo, dhi, ds);
            lg[kj] = dlo + dhi + brow[kj];
            rmax = fmaxf(rmax, lg[kj]);
        }
        const float mn = fmaxf(m, rmax);
        const float f  = __expf(m - mn);
        m = mn;
        s *= f;
        unsigned long long fp;
        PK2(fp, f, f);
#pragma unroll
        for (int u = 0; u < 16; u++) MUL2(accp[u], accp[u], fp);
#pragma unroll
        for (int kj = 0; kj < K; kj++) {
            const float p = __expf(lg[kj] - m);
            s += p;
            unsigned long long pp;
            PK2(pp, p, p);
            const ulonglong2* vp2 = (const ulonglong2*)&sv[(sj + kj)*36];
#pragma unroll
            for (int u = 0; u < 8; u++) {
                ulonglong2 vv = vp2[u];
                FMA2(accp[2*u+0], pp, vv.x, accp[2*u+0]);
                FMA2(accp[2*u+1], pp, vv.y, accp[2*u+1]);
            }
        }
    }

    const float inv = 1.f / s;
    unsigned long long ip;
    PK2(ip, inv, inv);
    float* op = g_y + (((size_t)b*4096) + i*64 + t)*256 + head*32;
#pragma unroll
    for (int u = 0; u < 8; u++) {
        ulonglong2 o;
        MUL2(o.x, accp[2*u+0], ip);
        MUL2(o.y, accp[2*u+1], ip);
        *(ulonglong2*)&op[u*4] = o;
    }
}

__global__ __launch_bounds__(64) void na_attn_fused(const float* __restrict__ rpb0,
                                                    const float* __restrict__ rpb1) {
    __shared__ float sk[64*36];
    __shared__ float sv[64*36];
    __shared__ float sb[25*25];
    const int hy = blockIdx.y;
    if (hy < 4) {
        na_attn_body<7>(rpb0, hy, hy, sk, sv, sb);
    } else {
        na_attn_body<13>(rpb1, hy - 4, hy, sk, sv, sb);
    }
}

// ---------------------------------------------------------------------------
extern "C" void kernel_launch(void* const* d_in, const int* in_sizes, int n_in,
                              void* d_out, int out_size) {
    const float* x      = (const float*)d_in[0];
    const float* w_qkv  = (const float*)d_in[1];
    const float* b_qkv  = (const float*)d_in[2];
    const float* rpb0   = (const float*)d_in[3];
    const float* rpb1   = (const float*)d_in[4];
    const float* w_proj = (const float*)d_in[5];
    const float* b_proj = (const float*)d_in[6];
    float* out = (float*)d_out;

    dim3 g1(NTOK/128, 768/128);
    qkv_gemm<<<g1, 256>>>(x, w_qkv, b_qkv);

    dim3 ga(HH, NHEADS, Bb);
    na_attn_fused<<<ga, 64>>>(rpb0, rpb1);

    dim3 g2(NTOK/128, 256/128);
    proj_gemm<<<g2, 256>>>(w_proj, b_proj, out);
}

// round 10
// speedup vs baseline: 1.5192x; 1.1375x over previous
#include <cuda_runtime.h>
#include <cuda_bf16.h>
#include <cstdint>

#define Bb 8
#define HH 64
#define WW 64
#define CC 256
#define NHEADS 8
#define DD 32
#define NTOK (Bb*HH*WW)   // 32768
#define QSCALE 0.17677669529663687f  // 32^-0.5

// scratch: [3][B*NH][H*W][D] for q,k,v ; [NTOK][C] for attention output
__device__ float g_qkv[(size_t)3*Bb*NHEADS*HH*WW*DD];
__device__ float g_y[(size_t)NTOK*CC];

// ---- packed f32x2 helpers (issue-slot savings; 2x independent fma.rn) ----
#define PK2(d, lo, hi)  asm("mov.b64 %0, {%1, %2};" : "=l"(d) : "f"(lo), "f"(hi))
#define UPK2(lo, hi, s) asm("mov.b64 {%0, %1}, %2;" : "=f"(lo), "=f"(hi) : "l"(s))
#define FMA2(d, a, b, c) asm("fma.rn.f32x2 %0, %1, %2, %3;" : "=l"(d) : "l"(a), "l"(b), "l"(c))
#define MUL2(d, a, b)    asm("mul.rn.f32x2 %0, %1, %2;"     : "=l"(d) : "l"(a), "l"(b))
#define ADD2(d, a, b)    asm("add.rn.f32x2 %0, %1, %2;"     : "=l"(d) : "l"(a), "l"(b))

__device__ __forceinline__ uint32_t smem_u32(const void* p) {
    uint32_t a;
    asm("{ .reg .u64 t; cvta.to.shared.u64 t, %1; cvt.u32.u64 %0, t; }" : "=r"(a) : "l"(p));
    return a;
}

// ---- mma.sync bf16 (base sm_80+ PTX, legal on sm_103) ----
__device__ __forceinline__ void mma_bf16(float* c, const uint32_t* a, const uint32_t* b) {
    asm volatile(
        "mma.sync.aligned.m16n8k16.row.col.f32.bf16.bf16.f32 "
        "{%0,%1,%2,%3}, {%4,%5,%6,%7}, {%8,%9}, {%0,%1,%2,%3};"
        : "+f"(c[0]), "+f"(c[1]), "+f"(c[2]), "+f"(c[3])
        : "r"(a[0]), "r"(a[1]), "r"(a[2]), "r"(a[3]), "r"(b[0]), "r"(b[1]));
}
__device__ __forceinline__ void ldsm4(uint32_t* r, uint32_t addr) {
    asm volatile("ldmatrix.sync.aligned.m8n8.x4.shared.b16 {%0,%1,%2,%3}, [%4];"
        : "=r"(r[0]), "=r"(r[1]), "=r"(r[2]), "=r"(r[3]) : "r"(addr));
}

// fp32 -> bf16 hi + residual lo, 4 at a time, packed as 2x uint32 each
__device__ __forceinline__ void cvt4(float4 f, uint2& hi, uint2& lo) {
    float fs[4] = {f.x, f.y, f.z, f.w};
    uint32_t h[4], l[4];
#pragma unroll
    for (int i = 0; i < 4; i++) {
        __nv_bfloat16 hb = __float2bfloat16_rn(fs[i]);
        float r = fs[i] - __bfloat162float(hb);
        __nv_bfloat16 lb = __float2bfloat16_rn(r);
        h[i] = (uint32_t)__bfloat16_as_ushort(hb);
        l[i] = (uint32_t)__bfloat16_as_ushort(lb);
    }
    hi.x = h[0] | (h[1] << 16); hi.y = h[2] | (h[3] << 16);
    lo.x = l[0] | (l[1] << 16); lo.y = l[2] | (l[3] << 16);
}

// ===========================================================================
// Split-bf16 mma.sync GEMM: C[n,m] = sum_c A[n,c]*B[m,c], A/B [rows,256] fp32.
// Block: 128(tokens) x 128(features), 256 thr = 8 warps (wm=w%4 row32, wn=w/4
// col64). BK=32 single-buffered smem, row stride 40 bf16 (80B) => ldmatrix
// conflict-free. D = AhBh + AhBl + AlBh (fp32 accum). MODE 0 qkv, 1 proj.
// ===========================================================================
#define TROW 40   // bf16 elements per smem tile row (32 + 8 pad)

template<int MODE>
__global__ __launch_bounds__(256) void tc_gemm(const float* __restrict__ Ain,
                                               const float* __restrict__ Bw,
                                               const float* __restrict__ bias,
                                               float* __restrict__ outp) {
    __shared__ __align__(16) uint16_t sAh[128*TROW];
    __shared__ __align__(16) uint16_t sAl[128*TROW];
    __shared__ __align__(16) uint16_t sBh[128*TROW];
    __shared__ __align__(16) uint16_t sBl[128*TROW];

    const float* A = (MODE == 0) ? Ain : (const float*)g_y;

    const int n0 = blockIdx.x * 128;
    const int m0 = blockIdx.y * 128;
    const int t    = threadIdx.x;
    const int w    = t >> 5;
    const int lane = t & 31;
    const int wm = w & 3;        // 0..3: token rows wm*32
    const int wn = w >> 2;       // 0..1: feature cols wn*64

    const uint32_t bAh = smem_u32(sAh), bAl = smem_u32(sAl);
    const uint32_t bBh = smem_u32(sBh), bBl = smem_u32(sBl);

    // loader mapping: thread t loads rows (t>>3)+i*32, cols (t&7)*4 (+kc*32)
    const int ldrow = t >> 3;
    const int ldcol = (t & 7) * 4;
    const float* Ag = A  + (size_t)(n0 + ldrow) * 256 + ldcol;
    const float* Bg = Bw + (size_t)(m0 + ldrow) * 256 + ldcol;
    const uint32_t soff = (uint32_t)(ldrow * TROW + ldcol) * 2;  // byte offset

    float c[2][8][4];
#pragma unroll
    for (int i = 0; i < 2; i++)
#pragma unroll
        for (int j = 0; j < 8; j++)
#pragma unroll
            for (int e = 0; e < 4; e++) c[i][j][e] = 0.f;

    // ldmatrix per-lane addresses (byte offsets within tile)
    // A frag (16x16): groups of 8 lanes -> rows, k-halves
    const uint32_t aoff = (uint32_t)((wm*32 + (lane & 7) + ((lane >> 3) & 1)*8) * TROW
                                     + (lane >> 4)*8) * 2;
    // B frag: lane l -> n row (wn*64 + g*32 + l), col half h*8
    const uint32_t boff0 = (uint32_t)((wn*64 + lane) * TROW) * 2;

    float4 pa[4], pb[4];
#pragma unroll
    for (int i = 0; i < 4; i++) {
        pa[i] = *(const float4*)(Ag + i*32*256);
        pb[i] = *(const float4*)(Bg + i*32*256);
    }

#pragma unroll 1
    for (int kc = 0; kc < 8; kc++) {
        __syncthreads();   // previous chunk consumed
#pragma unroll
        for (int i = 0; i < 4; i++) {
            uint2 hi, lo;
            cvt4(pa[i], hi, lo);
            *(uint2*)((char*)sAh + soff + i*32*TROW*2) = hi;
            *(uint2*)((char*)sAl + soff + i*32*TROW*2) = lo;
            cvt4(pb[i], hi, lo);
            *(uint2*)((char*)sBh + soff + i*32*TROW*2) = hi;
            *(uint2*)((char*)sBl + soff + i*32*TROW*2) = lo;
        }
        if (kc < 7) {
#pragma unroll
            for (int i = 0; i < 4; i++) {
                pa[i] = *(const float4*)(Ag + i*32*256 + (kc+1)*32);
                pb[i] = *(const float4*)(Bg + i*32*256 + (kc+1)*32);
            }
        }
        __syncthreads();

#pragma unroll
        for (int s = 0; s < 2; s++) {
            const uint32_t ks = (uint32_t)(s*16)*2;
            uint32_t ah[2][4], al[2][4];
#pragma unroll
            for (int i = 0; i < 2; i++) {
                ldsm4(ah[i], bAh + aoff + (uint32_t)(i*16*TROW)*2 + ks);
                ldsm4(al[i], bAl + aoff + (uint32_t)(i*16*TROW)*2 + ks);
            }
            uint32_t bh[8][2], bl[8][2];
#pragma unroll
            for (int g = 0; g < 2; g++) {
#pragma unroll
                for (int h = 0; h < 2; h++) {
                    uint32_t r[4];
                    ldsm4(r, bBh + boff0 + (uint32_t)(g*32*TROW)*2 + ks + (uint32_t)(h*8)*2);
#pragma unroll
                    for (int jj = 0; jj < 4; jj++) bh[g*4+jj][h] = r[jj];
                    ldsm4(r, bBl + boff0 + (uint32_t)(g*32*TROW)*2 + ks + (uint32_t)(h*8)*2);
#pragma unroll
                    for (int jj = 0; jj < 4; jj++) bl[g*4+jj][h] = r[jj];
                }
            }
#pragma unroll
            for (int j = 0; j < 8; j++) {
#pragma unroll
                for (int i = 0; i < 2; i++) {
                    mma_bf16(c[i][j], ah[i], bh[j]);
                    mma_bf16(c[i][j], ah[i], bl[j]);
                    mma_bf16(c[i][j], al[i], bh[j]);
                }
            }
        }
    }

    // ---- epilogue ----
#pragma unroll
    for (int i = 0; i < 2; i++) {
#pragma unroll
        for (int j = 0; j < 8; j++) {
            const int nb = n0 + wm*32 + i*16 + (lane >> 2);
            const int mb = m0 + wn*64 + j*8 + (lane & 3)*2;
            if (MODE == 0) {
#pragma unroll
                for (int e = 0; e < 4; e++) {
                    const int n = nb + (e >> 1)*8;
                    const int m = mb + (e & 1);
                    float val = c[i][j][e] + bias[m];
                    const int b  = n >> 12;
                    const int ij = n & 4095;
                    const int tsel = m >> 8;
                    const int hm   = m & 255;
                    const int head = hm >> 5;
                    const int dd   = hm & 31;
                    if (tsel == 0) val *= QSCALE;
                    const size_t idx = (((size_t)(tsel*64 + b*8 + head)) * 4096 + ij) * 32 + dd;
                    g_qkv[idx] = val;
                }
            } else {
                const float b0 = bias[mb], b1 = bias[mb+1];
                float2 o0 = make_float2(c[i][j][0] + b0, c[i][j][1] + b1);
                float2 o1 = make_float2(c[i][j][2] + b0, c[i][j][3] + b1);
                *(float2*)&outp[(size_t)nb*256 + mb]       = o0;
                *(float2*)&outp[(size_t)(nb+8)*256 + mb]   = o1;
            }
        }
    }
}

// ---------------------------------------------------------------------------
// Neighborhood attention (unchanged from R9 passing version).
// ---------------------------------------------------------------------------
template<int K>
__device__ __forceinline__ void na_attn_body(const float* __restrict__ rpb,
                                             int hl, int head,
                                             float* sk, float* sv, float* sb) {
    constexpr int R  = 2*K - 1;
    constexpr int NHf = K/2;

    const int i  = blockIdx.x;
    const int b  = blockIdx.z;
    const int t = threadIdx.x;   // query column j

    for (int u = t; u < R*R; u += 64) sb[u] = rpb[(size_t)hl*R*R + u];

    const int bh = b*NHEADS + head;
    const float* qb = g_qkv + ((size_t)(      bh) * 4096) * 32;
    const float* kb = g_qkv + ((size_t)( 64 + bh) * 4096) * 32;
    const float* vb = g_qkv + ((size_t)(128 + bh) * 4096) * 32;

    ulonglong2 q2[8];
    {
        const ulonglong2* qp = (const ulonglong2*)(qb + ((size_t)i*64 + t)*32);
#pragma unroll
        for (int u = 0; u < 8; u++) q2[u] = qp[u];
    }

    const int si  = min(max(i - NHf, 0), HH - K);
    const int sj  = min(max(t - NHf, 0), WW - K);
    const int pbi = si - i + K - 1;
    const int pbj = sj - t + K - 1;

    float m = -1e30f, s = 0.f;
    unsigned long long accp[16];
#pragma unroll
    for (int u = 0; u < 16; u++) accp[u] = 0ull;

#pragma unroll 1
    for (int ki = 0; ki < K; ki++) {
        const int row = si + ki;
        const float* krow = kb + ((size_t)row*64)*32;
        const float* vrow = vb + ((size_t)row*64)*32;
        __syncthreads();
#pragma unroll
        for (int u = 0; u < 8; u++) {
            const int idx = u*256 + t*4;
            const int col = idx >> 5, dd = idx & 31;
            *(float4*)&sk[col*36 + dd] = *(const float4*)&krow[idx];
            *(float4*)&sv[col*36 + dd] = *(const float4*)&vrow[idx];
        }
        __syncthreads();

        const float* brow = &sb[(pbi + ki)*R + pbj];
        float lg[K];
        float rmax = -1e30f;
#pragma unroll
        for (int kj = 0; kj < K; kj++) {
            const ulonglong2* kp2 = (const ulonglong2*)&sk[(sj + kj)*36];
            unsigned long long d0 = 0ull, d1 = 0ull;
#pragma unroll
            for (int u = 0; u < 8; u++) {
                ulonglong2 kv = kp2[u];
                FMA2(d0, q2[u].x, kv.x, d0);
                FMA2(d1, q2[u].y, kv.y, d1);
            }
            unsigned long long ds;
            ADD2(ds, d0, d1);
            float dlo, dhi;
            UPK2(dlo, dhi, ds);
            lg[kj] = dlo + dhi + brow[kj];
            rmax = fmaxf(rmax, lg[kj]);
        }
        const float mn = fmaxf(m, rmax);
        const float f  = __expf(m - mn);
        m = mn;
        s *= f;
        unsigned long long fp;
        PK2(fp, f, f);
#pragma unroll
        for (int u = 0; u < 16; u++) MUL2(accp[u], accp[u], fp);
#pragma unroll
        for (int kj = 0; kj < K; kj++) {
            const float p = __expf(lg[kj] - m);
            s += p;
            unsigned long long pp;
            PK2(pp, p, p);
            const ulonglong2* vp2 = (const ulonglong2*)&sv[(sj + kj)*36];
#pragma unroll
            for (int u = 0; u < 8; u++) {
                ulonglong2 vv = vp2[u];
                FMA2(accp[2*u+0], pp, vv.x, accp[2*u+0]);
                FMA2(accp[2*u+1], pp, vv.y, accp[2*u+1]);
            }
        }
    }

    const float inv = 1.f / s;
    unsigned long long ip;
    PK2(ip, inv, inv);
    float* op = g_y + (((size_t)b*4096) + i*64 + t)*256 + head*32;
#pragma unroll
    for (int u = 0; u < 8; u++) {
        ulonglong2 o;
        MUL2(o.x, accp[2*u+0], ip);
        MUL2(o.y, accp[2*u+1], ip);
        *(ulonglong2*)&op[u*4] = o;
    }
}

__global__ __launch_bounds__(64) void na_attn_fused(const float* __restrict__ rpb0,
                                                    const float* __restrict__ rpb1) {
    __shared__ float sk[64*36];
    __shared__ float sv[64*36];
    __shared__ float sb[25*25];
    const int hy = blockIdx.y;
    if (hy < 4) {
        na_attn_body<7>(rpb0, hy, hy, sk, sv, sb);
    } else {
        na_attn_body<13>(rpb1, hy - 4, hy, sk, sv, sb);
    }
}

// ---------------------------------------------------------------------------
extern "C" void kernel_launch(void* const* d_in, const int* in_sizes, int n_in,
                              void* d_out, int out_size) {
    const float* x      = (const float*)d_in[0];
    const float* w_qkv  = (const float*)d_in[1];
    const float* b_qkv  = (const float*)d_in[2];
    const float* rpb0   = (const float*)d_in[3];
    const float* rpb1   = (const float*)d_in[4];
    const float* w_proj = (const float*)d_in[5];
    const float* b_proj = (const float*)d_in[6];
    float* out = (float*)d_out;

    tc_gemm<0><<<dim3(NTOK/128, 768/128), 256>>>(x, w_qkv, b_qkv, nullptr);

    dim3 ga(HH, NHEADS, Bb);
    na_attn_fused<<<ga, 64>>>(rpb0, rpb1);

    tc_gemm<1><<<dim3(NTOK/128, 256/128), 256>>>(nullptr, w_proj, b_proj, out);
}

// round 16
// speedup vs baseline: 1.6057x; 1.0569x over previous
#include <cuda_runtime.h>
#include <cuda_bf16.h>
#include <cstdint>

#define Bb 8
#define HH 64
#define WW 64
#define CC 256
#define NHEADS 8
#define DD 32
#define NTOK (Bb*HH*WW)   // 32768
#define QSCALE 0.17677669529663687f  // 32^-0.5

// scratch: [3][B*NH][H*W][D] for q,k,v ; [NTOK][C] for attention output
__device__ float g_qkv[(size_t)3*Bb*NHEADS*HH*WW*DD];
__device__ float g_y[(size_t)NTOK*CC];

// ---- packed f32x2 helpers ----
#define PK2(d, lo, hi)  asm("mov.b64 %0, {%1, %2};" : "=l"(d) : "f"(lo), "f"(hi))
#define UPK2(lo, hi, s) asm("mov.b64 {%0, %1}, %2;" : "=f"(lo), "=f"(hi) : "l"(s))
#define FMA2(d, a, b, c) asm("fma.rn.f32x2 %0, %1, %2, %3;" : "=l"(d) : "l"(a), "l"(b), "l"(c))
#define MUL2(d, a, b)    asm("mul.rn.f32x2 %0, %1, %2;"     : "=l"(d) : "l"(a), "l"(b))
#define ADD2(d, a, b)    asm("add.rn.f32x2 %0, %1, %2;"     : "=l"(d) : "l"(a), "l"(b))

__device__ __forceinline__ uint32_t smem_u32(const void* p) {
    uint32_t a;
    asm("{ .reg .u64 t; cvta.to.shared.u64 t, %1; cvt.u32.u64 %0, t; }" : "=r"(a) : "l"(p));
    return a;
}

// ---- mma.sync bf16 (base sm_80+ PTX, legal on sm_103) ----
__device__ __forceinline__ void mma_bf16(float* c, const uint32_t* a, const uint32_t* b) {
    asm volatile(
        "mma.sync.aligned.m16n8k16.row.col.f32.bf16.bf16.f32 "
        "{%0,%1,%2,%3}, {%4,%5,%6,%7}, {%8,%9}, {%0,%1,%2,%3};"
        : "+f"(c[0]), "+f"(c[1]), "+f"(c[2]), "+f"(c[3])
        : "r"(a[0]), "r"(a[1]), "r"(a[2]), "r"(a[3]), "r"(b[0]), "r"(b[1]));
}
__device__ __forceinline__ void ldsm4(uint32_t* r, uint32_t addr) {
    asm volatile("ldmatrix.sync.aligned.m8n8.x4.shared.b16 {%0,%1,%2,%3}, [%4];"
        : "=r"(r[0]), "=r"(r[1]), "=r"(r[2]), "=r"(r[3]) : "r"(addr));
}

// fp32 -> bf16 hi + residual lo, 4 at a time, packed as 2x uint32 each
__device__ __forceinline__ void cvt4(float4 f, uint2& hi, uint2& lo) {
    float fs[4] = {f.x, f.y, f.z, f.w};
    uint32_t h[4], l[4];
#pragma unroll
    for (int i = 0; i < 4; i++) {
        __nv_bfloat16 hb = __float2bfloat16_rn(fs[i]);
        float r = fs[i] - __bfloat162float(hb);
        __nv_bfloat16 lb = __float2bfloat16_rn(r);
        h[i] = (uint32_t)__bfloat16_as_ushort(hb);
        l[i] = (uint32_t)__bfloat16_as_ushort(lb);
    }
    hi.x = h[0] | (h[1] << 16); hi.y = h[2] | (h[3] << 16);
    lo.x = l[0] | (l[1] << 16); lo.y = l[2] | (l[3] << 16);
}

// ===========================================================================
// Split-bf16 mma.sync GEMM, DOUBLE-BUFFERED smem, one sync per K32 chunk.
// C[n,m] = sum_c A[n,c]*B[m,c], A/B [rows,256] fp32. Block 128x128, 8 warps.
// D = AhBh + AhBl + AlBh (fp32 accum). MODE 0 qkv-scatter, 1 proj.
// ===========================================================================
#define TROW 40            // bf16 elems per smem row (32 + 8 pad; ldsm conflict-free)
#define ARRSZ (128*TROW*2) // 10240 B per array
#define BUFSZ (4*ARRSZ)    // 40960 B per buffer
#define OAh 0
#define OAl ARRSZ
#define OBh (2*ARRSZ)
#define OBl (3*ARRSZ)
#define TCG_SMEM (2*BUFSZ) // 81920 B

template<int MODE>
__global__ __launch_bounds__(256) void tc_gemm(const float* __restrict__ Ain,
                                               const float* __restrict__ Bw,
                                               const float* __restrict__ bias,
                                               float* __restrict__ outp) {
    extern __shared__ __align__(16) char dsm[];
    const float* A = (MODE == 0) ? Ain : (const float*)g_y;

    const int n0 = blockIdx.x * 128;
    const int m0 = blockIdx.y * 128;
    const int t    = threadIdx.x;
    const int w    = t >> 5;
    const int lane = t & 31;
    const int wm = w & 3;        // token rows wm*32
    const int wn = w >> 2;       // feature cols wn*64

    const uint32_t sb = smem_u32(dsm);

    const int ldrow = t >> 3;
    const int ldcol = (t & 7) * 4;
    const float* Ag = A  + (size_t)(n0 + ldrow) * 256 + ldcol;
    const float* Bg = Bw + (size_t)(m0 + ldrow) * 256 + ldcol;
    const uint32_t soff = (uint32_t)(ldrow * TROW + ldcol) * 2;

    float c[2][8][4];
#pragma unroll
    for (int i = 0; i < 2; i++)
#pragma unroll
        for (int j = 0; j < 8; j++)
#pragma unroll
            for (int e = 0; e < 4; e++) c[i][j][e] = 0.f;

    const uint32_t aoff = (uint32_t)((wm*32 + (lane & 7) + ((lane >> 3) & 1)*8) * TROW
                                     + (lane >> 4)*8) * 2;
    const uint32_t boff0 = (uint32_t)((wn*64 + lane) * TROW) * 2;

    float4 pa[4], pb[4];

#define PREFETCH(KC) do { _Pragma("unroll")                                    \
    for (int i_ = 0; i_ < 4; i_++) {                                           \
        pa[i_] = *(const float4*)(Ag + i_*32*256 + (KC)*32);                   \
        pb[i_] = *(const float4*)(Bg + i_*32*256 + (KC)*32); } } while(0)

#define STOREBUF(BUF) do { char* base_ = dsm + (BUF)*BUFSZ; _Pragma("unroll")  \
    for (int i_ = 0; i_ < 4; i_++) { uint2 hi_, lo_;                           \
        cvt4(pa[i_], hi_, lo_);                                                \
        *(uint2*)(base_ + OAh + soff + i_*32*TROW*2) = hi_;                    \
        *(uint2*)(base_ + OAl + soff + i_*32*TROW*2) = lo_;                    \
        cvt4(pb[i_], hi_, lo_);                                                \
        *(uint2*)(base_ + OBh + soff + i_*32*TROW*2) = hi_;                    \
        *(uint2*)(base_ + OBl + soff + i_*32*TROW*2) = lo_; } } while(0)

    PREFETCH(0);
    STOREBUF(0);
    PREFETCH(1);
    __syncthreads();

#pragma unroll 2
    for (int kc = 0; kc < 8; kc++) {
        const uint32_t bb = sb + (uint32_t)(kc & 1) * BUFSZ;
#pragma unroll
        for (int s = 0; s < 2; s++) {
            const uint32_t ks = (uint32_t)(s * 32);     // s*16 bf16 * 2B
            uint32_t ah[2][4], al[2][4];
#pragma unroll
            for (int i = 0; i < 2; i++) {
                ldsm4(ah[i], bb + OAh + aoff + (uint32_t)(i*16*TROW)*2 + ks);
                ldsm4(al[i], bb + OAl + aoff + (uint32_t)(i*16*TROW)*2 + ks);
            }
            uint32_t bh[8][2], bl[8][2];
#pragma unroll
            for (int g = 0; g < 2; g++) {
#pragma unroll
                for (int h = 0; h < 2; h++) {
                    uint32_t r[4];
                    ldsm4(r, bb + OBh + boff0 + (uint32_t)(g*32*TROW)*2 + ks + (uint32_t)(h*16));
#pragma unroll
                    for (int jj = 0; jj < 4; jj++) bh[g*4+jj][h] = r[jj];
                    ldsm4(r, bb + OBl + boff0 + (uint32_t)(g*32*TROW)*2 + ks + (uint32_t)(h*16));
#pragma unroll
                    for (int jj = 0; jj < 4; jj++) bl[g*4+jj][h] = r[jj];
                }
            }
#pragma unroll
            for (int j = 0; j < 8; j++) {
#pragma unroll
                for (int i = 0; i < 2; i++) {
                    mma_bf16(c[i][j], ah[i], bh[j]);
                    mma_bf16(c[i][j], ah[i], bl[j]);
                    mma_bf16(c[i][j], al[i], bh[j]);
                }
            }
        }
        if (kc < 7) STOREBUF((kc+1) & 1);
        if (kc < 6) PREFETCH(kc+2);
        __syncthreads();
    }

    // ---- epilogue ----
#pragma unroll
    for (int i = 0; i < 2; i++) {
#pragma unroll
        for (int j = 0; j < 8; j++) {
            const int nb = n0 + wm*32 + i*16 + (lane >> 2);
            const int mb = m0 + wn*64 + j*8 + (lane & 3)*2;
            if (MODE == 0) {
                const int tsel = mb >> 8;
                const int hm   = mb & 255;
                const int head = hm >> 5;
                const int dd   = hm & 31;          // even; dd+1 same head
                const float sc = (tsel == 0) ? QSCALE : 1.f;
                const float b0 = bias[mb], b1 = bias[mb+1];
#pragma unroll
                for (int e2 = 0; e2 < 2; e2++) {
                    const int n  = nb + e2*8;
                    const int b  = n >> 12;
                    const int ij = n & 4095;
                    float2 o;
                    o.x = (c[i][j][e2*2+0] + b0) * sc;
                    o.y = (c[i][j][e2*2+1] + b1) * sc;
                    const size_t idx = (((size_t)(tsel*64 + b*8 + head)) * 4096 + ij) * 32 + dd;
                    *(float2*)&g_qkv[idx] = o;
                }
            } else {
                const float b0 = bias[mb], b1 = bias[mb+1];
                float2 o0 = make_float2(c[i][j][0] + b0, c[i][j][1] + b1);
                float2 o1 = make_float2(c[i][j][2] + b0, c[i][j][3] + b1);
                *(float2*)&outp[(size_t)nb*256 + mb]       = o0;
                *(float2*)&outp[(size_t)(nb+8)*256 + mb]   = o1;
            }
        }
    }
}

// ---------------------------------------------------------------------------
// Neighborhood attention (unchanged from R10 passing version).
// ---------------------------------------------------------------------------
template<int K>
__device__ __forceinline__ void na_attn_body(const float* __restrict__ rpb,
                                             int hl, int head,
                                             float* sk, float* sv, float* sb) {
    constexpr int R  = 2*K - 1;
    constexpr int NHf = K/2;

    const int i  = blockIdx.x;
    const int b  = blockIdx.z;
    const int t = threadIdx.x;   // query column j

    for (int u = t; u < R*R; u += 64) sb[u] = rpb[(size_t)hl*R*R + u];

    const int bh = b*NHEADS + head;
    const float* qb = g_qkv + ((size_t)(      bh) * 4096) * 32;
    const float* kb = g_qkv + ((size_t)( 64 + bh) * 4096) * 32;
    const float* vb = g_qkv + ((size_t)(128 + bh) * 4096) * 32;

    ulonglong2 q2[8];
    {
        const ulonglong2* qp = (const ulonglong2*)(qb + ((size_t)i*64 + t)*32);
#pragma unroll
        for (int u = 0; u < 8; u++) q2[u] = qp[u];
    }

    const int si  = min(max(i - NHf, 0), HH - K);
    const int sj  = min(max(t - NHf, 0), WW - K);
    const int pbi = si - i + K - 1;
    const int pbj = sj - t + K - 1;

    float m = -1e30f, s = 0.f;
    unsigned long long accp[16];
#pragma unroll
    for (int u = 0; u < 16; u++) accp[u] = 0ull;

#pragma unroll 1
    for (int ki = 0; ki < K; ki++) {
        const int row = si + ki;
        const float* krow = kb + ((size_t)row*64)*32;
        const float* vrow = vb + ((size_t)row*64)*32;
        __syncthreads();
#pragma unroll
        for (int u = 0; u < 8; u++) {
            const int idx = u*256 + t*4;
            const int col = idx >> 5, dd = idx & 31;
            *(float4*)&sk[col*36 + dd] = *(const float4*)&krow[idx];
            *(float4*)&sv[col*36 + dd] = *(const float4*)&vrow[idx];
        }
        __syncthreads();

        const float* brow = &sb[(pbi + ki)*R + pbj];
        float lg[K];
        float rmax = -1e30f;
#pragma unroll
        for (int kj = 0; kj < K; kj++) {
            const ulonglong2* kp2 = (const ulonglong2*)&sk[(sj + kj)*36];
            unsigned long long d0 = 0ull, d1 = 0ull;
#pragma unroll
            for (int u = 0; u < 8; u++) {
                ulonglong2 kv = kp2[u];
                FMA2(d0, q2[u].x, kv.x, d0);
                FMA2(d1, q2[u].y, kv.y, d1);
            }
            unsigned long long ds;
            ADD2(ds, d0, d1);
            float dlo, dhi;
            UPK2(dlo, dhi, ds);
            lg[kj] = dlo + dhi + brow[kj];
            rmax = fmaxf(rmax, lg[kj]);
        }
        const float mn = fmaxf(m, rmax);
        const float f  = __expf(m - mn);
        m = mn;
        s *= f;
        unsigned long long fp;
        PK2(fp, f, f);
#pragma unroll
        for (int u = 0; u < 16; u++) MUL2(accp[u], accp[u], fp);
#pragma unroll
        for (int kj = 0; kj < K; kj++) {
            const float p = __expf(lg[kj] - m);
            s += p;
            unsigned long long pp;
            PK2(pp, p, p);
            const ulonglong2* vp2 = (const ulonglong2*)&sv[(sj + kj)*36];
#pragma unroll
            for (int u = 0; u < 8; u++) {
                ulonglong2 vv = vp2[u];
                FMA2(accp[2*u+0], pp, vv.x, accp[2*u+0]);
                FMA2(accp[2*u+1], pp, vv.y, accp[2*u+1]);
            }
        }
    }

    const float inv = 1.f / s;
    unsigned long long ip;
    PK2(ip, inv, inv);
    float* op = g_y + (((size_t)b*4096) + i*64 + t)*256 + head*32;
#pragma unroll
    for (int u = 0; u < 8; u++) {
        ulonglong2 o;
        MUL2(o.x, accp[2*u+0], ip);
        MUL2(o.y, accp[2*u+1], ip);
        *(ulonglong2*)&op[u*4] = o;
    }
}

__global__ __launch_bounds__(64) void na_attn_fused(const float* __restrict__ rpb0,
                                                    const float* __restrict__ rpb1) {
    __shared__ float sk[64*36];
    __shared__ float sv[64*36];
    __shared__ float sb[25*25];
    const int hy = blockIdx.y;
    if (hy < 4) {
        na_attn_body<7>(rpb0, hy, hy, sk, sv, sb);
    } else {
        na_attn_body<13>(rpb1, hy - 4, hy, sk, sv, sb);
    }
}

// ---------------------------------------------------------------------------
extern "C" void kernel_launch(void* const* d_in, const int* in_sizes, int n_in,
                              void* d_out, int out_size) {
    const float* x      = (const float*)d_in[0];
    const float* w_qkv  = (const float*)d_in[1];
    const float* b_qkv  = (const float*)d_in[2];
    const float* rpb0   = (const float*)d_in[3];
    const float* rpb1   = (const float*)d_in[4];
    const float* w_proj = (const float*)d_in[5];
    const float* b_proj = (const float*)d_in[6];
    float* out = (float*)d_out;

    cudaFuncSetAttribute(tc_gemm<0>, cudaFuncAttributeMaxDynamicSharedMemorySize, TCG_SMEM);
    cudaFuncSetAttribute(tc_gemm<1>, cudaFuncAttributeMaxDynamicSharedMemorySize, TCG_SMEM);

    tc_gemm<0><<<dim3(NTOK/128, 768/128), 256, TCG_SMEM>>>(x, w_qkv, b_qkv, nullptr);

    dim3 ga(HH, NHEADS, Bb);
    na_attn_fused<<<ga, 64>>>(rpb0, rpb1);

    tc_gemm<1><<<dim3(NTOK/128, 256/128), 256, TCG_SMEM>>>(nullptr, w_proj, b_proj, out);
}